// round 11
// baseline (speedup 1.0000x reference)
#include <cuda_runtime.h>
#include <math.h>

// ChfLoss: B=8, H=W=64, P=60. loss = (0.1/B) * sum_b ||CHF(dnn_b - gt_b)||_2
// Separable trig: angle[p,q,(i,j)] = r_q*x_i + r_p*y_j, x_axis == y_axis.
// ONE kernel, 120 blocks (1/SM). Multi-output threads: stage1 does 2 i per
// thread (float2 D-load), stage2 does 2 q per thread (float4 table load),
// halving smem instruction count vs R8. R9 bug fixed: D-load loop now covers
// all 1024 float4 (k<4 at NT=256); R9 only filled half of sD.

#define NB      8
#define HWD     64
#define PP      60
#define PTILES  15                  // 60 / 4 p-rows per block
#define NBLK    (NB * PTILES)       // 120
#define NT      256

// __device__ globals = sanctioned scratch (no allocation allowed)
__device__ float    g_part[NBLK];         // per-block partial sum of squares
__device__ unsigned g_count = 0;          // epilogue counter (self-resetting)

// Shared: D 4096 + CS 7680 + A 512 = 12288 floats = 48KB dynamic exactly.
// NO static __shared__ anywhere (would exceed the 48KB default limit).
__global__ __launch_bounds__(NT) void chf_fused_kernel(const float* __restrict__ dnn,
                                                       const float* __restrict__ gt,
                                                       float* __restrict__ out) {
    extern __shared__ float sm[];
    float*  sD  = sm;                               // [j*64 + i]
    float2* sCS = (float2*)(sm + 4096);             // [i*60 + q] (also [j*60 + p])
    float2* sA  = (float2*)(sm + 4096 + 7680);      // [i*4 + pl] = (Ac, As)

    const int blk = blockIdx.x;
    const int b   = blk / PTILES;
    const int pt  = blk - b * PTILES;
    const int p0  = pt * 4;
    const int t   = threadIdx.x;

    // ---- issue global loads FIRST (latency hidden by table gen below) ----
    const float4* d4 = (const float4*)(dnn + b * 4096);
    const float4* g4 = (const float4*)(gt  + b * 4096);
    float4 va[4], vg[4];
    #pragma unroll
    for (int k = 0; k < 4; k++) {                    // 4*256 = 1024 float4 = ALL of D
        va[k] = d4[t + k * NT];
        vg[k] = g4[t + k * NT];
    }

    // ---- full trig table, block-private, 15 entries/thread ----
    // Ref: angle = fl(r_q * x_i) fp32, then cos/sin. Exact fp32 Cody-Waite:
    // k = rint(a/2pi) (|k|<=243 exact); fma(-k, 6.28125f, a) EXACT (both
    // multiples of 2^-13, |diff|<=3.6); 2nd fma adds ~3e-7 rad. __sincosf on
    // |ar|<=pi: ~5e-7 abs. Loss rel_err ~1e-7..1e-6 << 1e-3. (R7-proven.)
    {
        const float inv2pi = 0.15915494309189535f;
        const float C1 = 6.28125f;                   // 201/32, exact
        const float C2 = 1.9353071795864769e-3f;     // 2*pi - C1
        #pragma unroll
        for (int k = 0; k < 15; k++) {
            int e = t + k * NT;                      // 0..3839 = i*60 + q
            int i = e / 60;
            int q = e - i * 60;
            float r  = (float)(q - 30) * 0.1f;       // fp32 grid, matches ref
            float x  = (float)(4 + 8 * i);           // linspace(4,508,64), exact
            float a  = r * x;                        // ref's fp32 angle
            float kk = rintf(a * inv2pi);
            float ar = fmaf(-kk, C1, a);             // exact
            ar       = fmaf(-kk, C2, ar);            // |ar| <= pi (+eps)
            float s, c;
            __sincosf(ar, &s, &c);
            sCS[e] = make_float2(c, s);              // consecutive -> conflict-free
        }
    }

    // ---- D = dnn - gt into shared ----
    {
        float4* sD4 = (float4*)sD;
        #pragma unroll
        for (int k = 0; k < 4; k++) {
            sD4[t + k * NT] = make_float4(va[k].x - vg[k].x, va[k].y - vg[k].y,
                                          va[k].z - vg[k].z, va[k].w - vg[k].w);
        }
    }
    __syncthreads();

    // ---- stage 1: t = pl*64 + ip*2 + jh -> 2 outputs (i = 2ip, 2ip+1) ----
    // Per iter: 1 LDS.64 (d pair) + 1 LDS.64 (cs) + 4 FMA for 2 outputs.
    {
        const int jh = t & 1;                        // j half
        const int ip = (t >> 1) & 31;                // i pair
        const int pl = t >> 6;
        const int p  = p0 + pl;
        const int j0 = jh * 32;
        const float2* sD2 = (const float2*)sD;       // [j*32 + ip]
        float ac0 = 0.f, ac1 = 0.f, as0 = 0.f, as1 = 0.f;
        #pragma unroll 16
        for (int jj = 0; jj < 32; jj++) {
            int j = j0 + jj;
            float2 d  = sD2[j * 32 + ip];
            float2 cs = sCS[j * PP + p];             // broadcast (p uniform/warp)
            ac0 = fmaf(cs.x, d.x, ac0);
            ac1 = fmaf(cs.x, d.y, ac1);
            as0 = fmaf(cs.y, d.x, as0);
            as1 = fmaf(cs.y, d.y, as1);
        }
        // combine j halves with partner lane (t^1): exact & deterministic
        ac0 += __shfl_xor_sync(0xFFFFFFFFu, ac0, 1);
        ac1 += __shfl_xor_sync(0xFFFFFFFFu, ac1, 1);
        as0 += __shfl_xor_sync(0xFFFFFFFFu, as0, 1);
        as1 += __shfl_xor_sync(0xFFFFFFFFu, as1, 1);
        if (!jh) {
            sA[(2 * ip + 0) * 4 + pl] = make_float2(ac0, as0);
            sA[(2 * ip + 1) * 4 + pl] = make_float2(ac1, as1);
        }
    }
    __syncthreads();

    // ---- stage 2: t<240: t = q2*8 + pl*2 + ih -> 2 outputs (q = 2q2, 2q2+1) ----
    // Per iter: 1 LDS.128 (cs for 2 q) + 1 LDS.64 (A) + 8 FMA for 2 outputs.
    float v = 0.f;
    {
        const int ih = t & 1;
        const int pl = (t >> 1) & 3;
        const int q2 = t >> 3;                       // 0..29 valid (t<240)
        float r0a = 0.f, r0b = 0.f, i0a = 0.f, i0b = 0.f;
        float r1a = 0.f, r1b = 0.f, i1a = 0.f, i1b = 0.f;
        if (q2 < 30) {
            const int istart = ih * 32;
            const float4* sCS4 = (const float4*)sCS; // [i*30 + q2] = q pair
            #pragma unroll 16
            for (int ii = 0; ii < 32; ii++) {
                int i = istart + ii;
                float2 a  = sA[i * 4 + pl];          // (Ac, As)
                float4 cs = sCS4[i * 30 + q2];       // (c_q0,s_q0,c_q1,s_q1)
                r0a = fmaf(a.x, cs.x, r0a);
                r0b = fmaf(a.y, cs.y, r0b);
                i0a = fmaf(a.y, cs.x, i0a);
                i0b = fmaf(a.x, cs.y, i0b);
                r1a = fmaf(a.x, cs.z, r1a);
                r1b = fmaf(a.y, cs.w, r1b);
                i1a = fmaf(a.y, cs.z, i1a);
                i1b = fmaf(a.x, cs.w, i1b);
            }
        }
        float re0 = r0a - r0b, im0 = i0a + i0b;
        float re1 = r1a - r1b, im1 = i1a + i1b;
        // combine i halves with partner lane (t^1): exact & deterministic
        re0 += __shfl_xor_sync(0xFFFFFFFFu, re0, 1);
        im0 += __shfl_xor_sync(0xFFFFFFFFu, im0, 1);
        re1 += __shfl_xor_sync(0xFFFFFFFFu, re1, 1);
        im1 += __shfl_xor_sync(0xFFFFFFFFu, im1, 1);
        if (!ih && q2 < 30)
            v = fmaf(re0, re0, im0 * im0) + fmaf(re1, re1, im1 * im1);
    }

    // ---- block reduce sum of squares ----
    #pragma unroll
    for (int off = 16; off > 0; off >>= 1)
        v += __shfl_down_sync(0xFFFFFFFFu, v, off);

    __syncthreads();                       // stage-2 smem reads done; reuse sD
    if ((t & 31) == 0) sD[t >> 5] = v;     // 8 warp partials
    __syncthreads();
    if (t == 0) {
        float s = 0.f;
        #pragma unroll
        for (int w = 0; w < 8; w++) s += sD[w];
        g_part[blk] = s;
        __threadfence();                   // release g_part before counter bump
        unsigned c = atomicAdd(&g_count, 1u);
        bool last = (c == NBLK - 1);
        if (last) g_count = 0;             // reset for next graph replay
        sD[8] = last ? 1.f : 0.f;          // flag via dynamic smem (no static shared)
    }
    __syncthreads();

    // ---- last block: deterministic finalize ----
    if (sD[8] != 0.f) {
        __threadfence();                   // acquire: all g_part visible
        float w = 0.f;
        if (t < NB) {
            float s = 0.f;
            #pragma unroll
            for (int k = 0; k < PTILES; k++)
                s += g_part[t * PTILES + k];   // fixed order -> deterministic
            w = sqrtf(s);
        }
        if (t < 32) {
            #pragma unroll
            for (int off = 16; off > 0; off >>= 1)
                w += __shfl_down_sync(0xFFFFFFFFu, w, off);
            if (t == 0) out[0] = w * 0.1f / 8.0f;
        }
    }
}

// ---------------------------------------------------------------------------
extern "C" void kernel_launch(void* const* d_in, const int* in_sizes, int n_in,
                              void* d_out, int out_size) {
    (void)in_sizes; (void)n_in; (void)out_size;
    const float* dnn = (const float*)d_in[0];
    const float* gt  = (const float*)d_in[1];
    float* out = (float*)d_out;

    chf_fused_kernel<<<NBLK, NT, 12288 * sizeof(float)>>>(dnn, gt, out);
}